// round 16
// baseline (speedup 1.0000x reference)
#include <cuda_runtime.h>
#include <cuda_fp16.h>
#include <cstdint>

#define BDIM   8192
#define KDIM   2336
#define KPAD   2368    // 37 * 64
#define NDIM   20000
#define ZW     2304
#define NPROW  2048
#define NAROW  256
#define NCROW  32

#define BM     128
#define BN     128
#define BK     64
#define NKT    37      // KPAD / BK
#define STAGES 3
#define GRID_M 64
#define GRID_N 158
#define NTILES (GRID_M * GRID_N)   // 10112
#define GROUP  16
#define NTHR   256     // 8 warps: 2 (m) x 4 (n), 64x32 warp tiles, 2 CTAs/SM
#define NCTA   296     // persistent: 2 per SM on 148 SMs

#define APITCH 272     // bytes per k-row of packed A tile (17*16)
#define BPITCH 272     // bytes per k-row of packed B tile (17*16)
#define A_TILE_B (BK * APITCH)   // 17408
#define B_TILE_B (BK * BPITCH)   // 17408
#define STAGE_B  (A_TILE_B + B_TILE_B)          // 34816
#define SMEM_BYTES (64 + STAGES * STAGE_B)      // 104512
#define PW      632    // 158 n-blocks * 4 n-warps

__device__ __align__(16) unsigned char g_Apack[(size_t)GRID_M * NKT * A_TILE_B];  // ~41 MB
__device__ __align__(16) unsigned char g_Wpack[(size_t)GRID_N * NKT * B_TILE_B];  // ~102 MB
__device__ float g_part[(size_t)BDIM * PW];    // ~20.7 MB
__device__ float g_scale[BDIM];

// ---------------------------------------------------------------------------
__device__ __forceinline__ uint32_t smem_u32(const void* p) {
    uint32_t a;
    asm("{ .reg .u64 t; cvta.to.shared.u64 t, %1; cvt.u32.u64 %0, t; }" : "=r"(a) : "l"(p));
    return a;
}
__device__ __forceinline__ void mbar_init(uint32_t m, uint32_t cnt) {
    asm volatile("mbarrier.init.shared.b64 [%0], %1;" :: "r"(m), "r"(cnt) : "memory");
}
__device__ __forceinline__ void mbar_arrive(uint32_t m) {
    asm volatile("mbarrier.arrive.release.cta.shared::cta.b64 _, [%0];" :: "r"(m) : "memory");
}
__device__ __forceinline__ void mbar_expect_tx(uint32_t m, uint32_t bytes) {
    asm volatile("mbarrier.arrive.expect_tx.shared.b64 _, [%0], %1;" :: "r"(m), "r"(bytes) : "memory");
}
__device__ __forceinline__ void mbar_wait(uint32_t m, uint32_t ph) {
    uint32_t done;
    asm volatile("{\n\t.reg .pred p;\n\tmbarrier.try_wait.parity.acquire.cta.shared::cta.b64 p, [%1], %2;\n\tselp.b32 %0, 1, 0, p;\n\t}"
                 : "=r"(done) : "r"(m), "r"(ph) : "memory");
    while (!done) {
        asm volatile("{\n\t.reg .pred p;\n\tmbarrier.try_wait.parity.acquire.cta.shared::cta.b64 p, [%1], %2, 0x989680;\n\tselp.b32 %0, 1, 0, p;\n\t}"
                     : "=r"(done) : "r"(m), "r"(ph) : "memory");
    }
}
__device__ __forceinline__ void bulk_g2s(uint32_t dst, const void* src, uint32_t bytes, uint32_t mbar) {
    asm volatile("cp.async.bulk.shared::cluster.global.mbarrier::complete_tx::bytes [%0], [%1], %2, [%3];"
                 :: "r"(dst), "l"(src), "r"(bytes), "r"(mbar) : "memory");
}
__device__ __forceinline__ void ldsm_x4_t(uint32_t* r, uint32_t addr) {
    asm volatile("ldmatrix.sync.aligned.m8n8.x4.trans.shared.b16 {%0,%1,%2,%3}, [%4];"
                 : "=r"(r[0]), "=r"(r[1]), "=r"(r[2]), "=r"(r[3]) : "r"(addr));
}
__device__ __forceinline__ void mma_f16(float* d, const uint32_t* a, const uint32_t* b) {
    asm volatile("mma.sync.aligned.m16n8k16.row.col.f32.f16.f16.f32 "
                 "{%0,%1,%2,%3}, {%4,%5,%6,%7}, {%8,%9}, {%0,%1,%2,%3};"
                 : "+f"(d[0]), "+f"(d[1]), "+f"(d[2]), "+f"(d[3])
                 : "r"(a[0]), "r"(a[1]), "r"(a[2]), "r"(a[3]), "r"(b[0]), "r"(b[1]));
}
__device__ __forceinline__ uint32_t pack_h2(float x, float y) {
    __half2 h = __float22half2_rn(make_float2(x, y));
    return *reinterpret_cast<uint32_t*>(&h);
}

// ---------------------------------------------------------------------------
// Pack A tiles: [mblk][kt] -> 64 k-rows x 272B (128 m fp16 + pad), smem transpose
__global__ void build_Apack_kernel(const float* __restrict__ z, const float* __restrict__ cov) {
    __shared__ __align__(16) __half s[BK][136];
    const int b = blockIdx.x;               // mblk*NKT + kt
    const int mblk = b / NKT, kt = b - mblk * NKT;
    const int m0 = mblk * BM, k0 = kt * BK;
    const int tid = threadIdx.x;
    for (int i = tid; i < BM * BK; i += 256) {
        int m = i >> 6, k = i & 63;
        int col = k0 + k;
        float v = 0.f;
        if (col < ZW)        v = z[(size_t)(m0 + m) * ZW + col];
        else if (col < KDIM) v = cov[(size_t)(m0 + m) * NCROW + (col - ZW)];
        s[k][m] = __float2half(v);
    }
    __syncthreads();
    unsigned char* dst = g_Apack + (size_t)b * A_TILE_B;
    for (int i = tid; i < BK * 17; i += 256) {
        int k = i / 17, c = i - k * 17;
        *reinterpret_cast<uint4*>(dst + k * APITCH + c * 16) =
            *reinterpret_cast<const uint4*>(&s[k][c * 8]);
    }
}

// Pack W tiles: [nblk][kt] -> 64 k-rows x 272B (128 n fp16 + pad), mask fused
__global__ void build_Wpack_kernel(const float* __restrict__ Wm, const float* __restrict__ mask,
                                   const float* __restrict__ Wa, const float* __restrict__ am,
                                   const float* __restrict__ Wc) {
    const size_t total = (size_t)GRID_N * NKT * BK * 17;     // 16B chunks
    size_t idx = (size_t)blockIdx.x * blockDim.x + threadIdx.x;
    if (idx >= total) return;
    int c    = (int)(idx % 17);
    size_t q = idx / 17;
    int k    = (int)(q % BK);
    size_t r = q / BK;
    int kt   = (int)(r % NKT);
    int nblk = (int)(r / NKT);
    unsigned char* dst = g_Wpack + ((size_t)nblk * NKT + kt) * B_TILE_B + k * BPITCH + c * 16;
    int kk = kt * BK + k;
    if (c == 16 || kk >= KDIM) {
        *reinterpret_cast<uint4*>(dst) = make_uint4(0, 0, 0, 0);
        return;
    }
    int n = nblk * BN + c * 8;
    float4 v0, v1;
    if (n + 7 >= NDIM) {
        float t[8];
#pragma unroll
        for (int j = 0; j < 8; j++) {
            int nn = n + j;
            float x = 0.f;
            if (nn < NDIM) {
                if (kk < NPROW)            x = Wm[(size_t)kk * NDIM + nn] * mask[(size_t)kk * NDIM + nn];
                else if (kk < NPROW+NAROW) x = Wa[(size_t)(kk-NPROW) * NDIM + nn] * am[(size_t)(kk-NPROW) * NDIM + nn];
                else                       x = Wc[(size_t)(kk-NPROW-NAROW) * NDIM + nn];
            }
            t[j] = x;
        }
        v0 = make_float4(t[0], t[1], t[2], t[3]);
        v1 = make_float4(t[4], t[5], t[6], t[7]);
    } else if (kk < NPROW) {
        float4 w0 = *reinterpret_cast<const float4*>(Wm + (size_t)kk * NDIM + n);
        float4 w1 = *reinterpret_cast<const float4*>(Wm + (size_t)kk * NDIM + n + 4);
        float4 m0 = *reinterpret_cast<const float4*>(mask + (size_t)kk * NDIM + n);
        float4 m1 = *reinterpret_cast<const float4*>(mask + (size_t)kk * NDIM + n + 4);
        v0 = make_float4(w0.x*m0.x, w0.y*m0.y, w0.z*m0.z, w0.w*m0.w);
        v1 = make_float4(w1.x*m1.x, w1.y*m1.y, w1.z*m1.z, w1.w*m1.w);
    } else if (kk < NPROW + NAROW) {
        int k2 = kk - NPROW;
        float4 w0 = *reinterpret_cast<const float4*>(Wa + (size_t)k2 * NDIM + n);
        float4 w1 = *reinterpret_cast<const float4*>(Wa + (size_t)k2 * NDIM + n + 4);
        float4 m0 = *reinterpret_cast<const float4*>(am + (size_t)k2 * NDIM + n);
        float4 m1 = *reinterpret_cast<const float4*>(am + (size_t)k2 * NDIM + n + 4);
        v0 = make_float4(w0.x*m0.x, w0.y*m0.y, w0.z*m0.z, w0.w*m0.w);
        v1 = make_float4(w1.x*m1.x, w1.y*m1.y, w1.z*m1.z, w1.w*m1.w);
    } else {
        int k2 = kk - NPROW - NAROW;
        v0 = *reinterpret_cast<const float4*>(Wc + (size_t)k2 * NDIM + n);
        v1 = *reinterpret_cast<const float4*>(Wc + (size_t)k2 * NDIM + n + 4);
    }
    uint4 o;
    o.x = pack_h2(v0.x, v0.y); o.y = pack_h2(v0.z, v0.w);
    o.z = pack_h2(v1.x, v1.y); o.w = pack_h2(v1.z, v1.w);
    *reinterpret_cast<uint4*>(dst) = o;
}

// ---------------------------------------------------------------------------
// Persistent fp16 mma.sync GEMM: 296 CTAs, each streams ~34 tiles of 128x128.
// 8 warps of 64x32, BK=64, 3-stage TMA ring that stays hot ACROSS tiles.
__global__ __launch_bounds__(NTHR, 2)
void gemm_exp_kernel(float* __restrict__ out) {
    extern __shared__ __align__(16) unsigned char smx[];
    const uint32_t sb0 = smem_u32(smx);          // [0..23] full, [32..55] free
    const int t   = threadIdx.x;
    const int wid = t >> 5;
    const int lid = t & 31;
    const int g4  = lid >> 2;
    const int tig = lid & 3;
    const int cta = blockIdx.x;

    const int wm = wid >> 2;      // 0..1
    const int wn = wid & 3;       // 0..3
    const int mbase = wm * 64;
    const int nbase = wn * 32;

    if (t == 0) {
#pragma unroll
        for (int s = 0; s < STAGES; s++) {
            mbar_init(sb0 + s * 8, 1);           // full: tx-based
            mbar_init(sb0 + 32 + s * 8, 8);      // free: 8 warp arrivals
        }
    }
    __syncthreads();

    const int per = GROUP * GRID_N;
    const int myTiles = (NTILES - 1 - cta) / NCTA + 1;
    const int totg = myTiles * NKT;

    // issue the stage holding global iter index gg (gg = tileOrd*NKT + kt)
    auto issue_g = [&](int slot, int gg) {
        const int ord  = gg / NKT;
        const int kt   = gg - ord * NKT;
        const int tile = cta + ord * NCTA;
        const int grp  = tile / per;
        const int loc  = tile - grp * per;
        const int pm   = grp * GROUP + (loc & (GROUP - 1));
        const int pn   = loc >> 4;
        const unsigned char* sA = g_Apack + ((size_t)pm * NKT + kt) * A_TILE_B;
        const unsigned char* sB = g_Wpack + ((size_t)pn * NKT + kt) * B_TILE_B;
        const uint32_t mb  = sb0 + slot * 8;
        const uint32_t stg = sb0 + 64 + slot * STAGE_B;
        mbar_expect_tx(mb, STAGE_B);
        bulk_g2s(stg,            sA, A_TILE_B, mb);
        bulk_g2s(stg + A_TILE_B, sB, B_TILE_B, mb);
    };

    if (t == 0) {
#pragma unroll
        for (int s = 0; s < STAGES; s++)
            if (s < totg) issue_g(s, s);
    }

    const int laneRow = (lid & 7) + ((lid >> 3) & 1) * 8;   // 0..15
    const int laneHi  = (lid >> 4);                          // 0 or 1
    const uint32_t offA = (uint32_t)laneRow * APITCH + (uint32_t)(mbase + laneHi * 8) * 2;
    const uint32_t offB = (uint32_t)laneRow * BPITCH + (uint32_t)(nbase + laneHi * 8) * 2;

    int ph = 0, fpown = 0, slot = 0, g = 0;
    const bool is_producer = (wid < STAGES) && (lid == 0);

    for (int tile = cta; tile < NTILES; tile += NCTA) {
        const int grp = tile / per;
        const int loc = tile - grp * per;
        const int pm  = grp * GROUP + (loc & (GROUP - 1));
        const int pn  = loc >> 4;
        const int m0  = pm * BM;
        const int n0  = pn * BN;

        float acc[4][4][4];
#pragma unroll
        for (int i = 0; i < 4; i++)
#pragma unroll
            for (int j = 0; j < 4; j++)
#pragma unroll
                for (int q = 0; q < 4; q++) acc[i][j][q] = 0.f;

        for (int kt = 0; kt < NKT; kt++, g++) {
            mbar_wait(sb0 + slot * 8, ph);

            const uint32_t stg = sb0 + 64 + slot * STAGE_B;
            const uint32_t pA = stg + offA;
            const uint32_t pB = stg + A_TILE_B + offB;

#pragma unroll
            for (int kk = 0; kk < BK; kk += 16) {
                uint32_t af[4][4], bf[4][2];
#pragma unroll
                for (int mf = 0; mf < 4; mf++) {
                    uint32_t r[4];
                    ldsm_x4_t(r, pA + kk * APITCH + mf * 32);
                    af[mf][0] = r[0]; af[mf][1] = r[2]; af[mf][2] = r[1]; af[mf][3] = r[3];
                }
#pragma unroll
                for (int nf2 = 0; nf2 < 2; nf2++) {
                    uint32_t r[4];
                    ldsm_x4_t(r, pB + kk * BPITCH + nf2 * 32);
                    bf[nf2 * 2][0]     = r[0]; bf[nf2 * 2][1]     = r[1];
                    bf[nf2 * 2 + 1][0] = r[2]; bf[nf2 * 2 + 1][1] = r[3];
                }
#pragma unroll
                for (int mf = 0; mf < 4; mf++)
#pragma unroll
                    for (int nf = 0; nf < 4; nf++)
                        mma_f16(acc[mf][nf], af[mf], bf[nf]);
            }

            if (lid == 0) mbar_arrive(sb0 + 32 + slot * 8);   // warp done w/ stage
            if (is_producer && wid == slot && g + STAGES < totg) {
                mbar_wait(sb0 + 32 + slot * 8, fpown);        // all 8 warps done
                issue_g(slot, g + STAGES);
                fpown ^= 1;
            }
            if (slot == STAGES - 1) { slot = 0; ph ^= 1; } else slot++;
        }

        // ---- register-direct epilogue (overlaps with next tile's prefetch) ----
#pragma unroll
        for (int mf = 0; mf < 4; mf++) {
            const int r0 = mbase + mf * 16 + g4;
            float* o0 = out + (size_t)(m0 + r0) * NDIM;
            float* o1 = o0 + (size_t)8 * NDIM;
            float s0 = 0.f, s1 = 0.f;
#pragma unroll
            for (int nf = 0; nf < 4; nf++) {
                const int n = n0 + nbase + nf * 8 + tig * 2;
                if (n < NDIM) {
                    float e0 = __expf(acc[mf][nf][0]);
                    float e1 = __expf(acc[mf][nf][1]);
                    float e2 = __expf(acc[mf][nf][2]);
                    float e3 = __expf(acc[mf][nf][3]);
                    *reinterpret_cast<float2*>(o0 + n) = make_float2(e0, e1);
                    *reinterpret_cast<float2*>(o1 + n) = make_float2(e2, e3);
                    s0 += e0 + e1; s1 += e2 + e3;
                }
            }
            s0 += __shfl_xor_sync(0xffffffffu, s0, 1);
            s0 += __shfl_xor_sync(0xffffffffu, s0, 2);
            s1 += __shfl_xor_sync(0xffffffffu, s1, 1);
            s1 += __shfl_xor_sync(0xffffffffu, s1, 2);
            if (tig == 0) {
                g_part[(size_t)(m0 + r0)     * PW + pn * 4 + wn] = s0;
                g_part[(size_t)(m0 + r0 + 8) * PW + pn * 4 + wn] = s1;
            }
        }
    }
}

// ---------------------------------------------------------------------------
__global__ void reduce_kernel(const float* __restrict__ loglib) {
    __shared__ float red[4];
    int row = blockIdx.x;
    float s = 0.f;
    for (int i = threadIdx.x; i < PW; i += 128) s += g_part[(size_t)row * PW + i];
#pragma unroll
    for (int o = 16; o > 0; o >>= 1) s += __shfl_down_sync(0xffffffffu, s, o);
    int lane = threadIdx.x & 31, warp = threadIdx.x >> 5;
    if (lane == 0) red[warp] = s;
    __syncthreads();
    if (threadIdx.x == 0) {
        float tot = red[0] + red[1] + red[2] + red[3];
        g_scale[row] = expf(loglib[row]) / tot;
    }
}

__global__ void scale_kernel(float* __restrict__ out) {
    const int RF4 = NDIM / 4;                   // 5000
    int row = blockIdx.y;
    int c4  = blockIdx.x * blockDim.x + threadIdx.x;
    if (c4 >= RF4) return;
    float s = g_scale[row];
    float4* p = reinterpret_cast<float4*>(out) + (size_t)row * RF4 + c4;
    float4 v = *p;
    v.x *= s; v.y *= s; v.z *= s; v.w *= s;
    *p = v;
}

// ---------------------------------------------------------------------------
extern "C" void kernel_launch(void* const* d_in, const int* in_sizes, int n_in,
                              void* d_out, int out_size) {
    const float* z      = (const float*)d_in[0];
    const float* loglib = (const float*)d_in[1];
    const float* cov    = (const float*)d_in[2];
    const float* mask   = (const float*)d_in[3];
    const float* amask  = (const float*)d_in[4];
    const float* Wm     = (const float*)d_in[5];
    const float* Wa     = (const float*)d_in[6];
    const float* Wc     = (const float*)d_in[7];
    float* out = (float*)d_out;

    cudaFuncSetAttribute(gemm_exp_kernel, cudaFuncAttributeMaxDynamicSharedMemorySize, SMEM_BYTES);

    build_Apack_kernel<<<GRID_M * NKT, 256>>>(z, cov);
    {
        size_t total = (size_t)GRID_N * NKT * BK * 17;
        build_Wpack_kernel<<<(unsigned)((total + 255) / 256), 256>>>(Wm, mask, Wa, amask, Wc);
    }
    gemm_exp_kernel<<<NCTA, NTHR, SMEM_BYTES>>>(out);
    reduce_kernel<<<BDIM, 128>>>(loglib);
    {
        dim3 gridS((NDIM / 4 + 255) / 256, BDIM, 1);
        scale_kernel<<<gridS, 256>>>(out);
    }
}

// round 17
// speedup vs baseline: 1.1092x; 1.1092x over previous
#include <cuda_runtime.h>
#include <cuda_fp16.h>
#include <cstdint>

#define BDIM   8192
#define KDIM   2336
#define KPAD   2368    // 37 * 64
#define NDIM   20000
#define ZW     2304
#define NPROW  2048
#define NAROW  256
#define NCROW  32

#define BM     128
#define BN     128
#define BK     64
#define NKT    37      // KPAD / BK
#define STAGES 3
#define GRID_M 64
#define GRID_N 158
#define GROUP  16
#define NTHR   256     // 8 warps: 2 (m) x 4 (n), 64x32 warp tiles, 2 CTAs/SM

#define APITCH 272     // bytes per k-row of packed A tile (17*16)
#define BPITCH 272     // bytes per k-row of packed B tile (17*16)
#define A_TILE_B (BK * APITCH)   // 17408
#define B_TILE_B (BK * BPITCH)   // 17408
#define STAGE_B  (A_TILE_B + B_TILE_B)          // 34816
#define SMEM_BYTES (64 + STAGES * STAGE_B)      // 104512
#define PW      632    // 158 n-blocks * 4 n-warps

__device__ __align__(16) unsigned char g_Apack[(size_t)GRID_M * NKT * A_TILE_B];  // ~41 MB
__device__ __align__(16) unsigned char g_Wpack[(size_t)GRID_N * NKT * B_TILE_B];  // ~102 MB
__device__ __align__(16) __half g_exp[(size_t)BDIM * NDIM];                       // ~327 MB
__device__ float g_part[(size_t)BDIM * PW];    // ~20.7 MB
__device__ float g_scale[BDIM];

// ---------------------------------------------------------------------------
__device__ __forceinline__ uint32_t smem_u32(const void* p) {
    uint32_t a;
    asm("{ .reg .u64 t; cvta.to.shared.u64 t, %1; cvt.u32.u64 %0, t; }" : "=r"(a) : "l"(p));
    return a;
}
__device__ __forceinline__ void mbar_init(uint32_t m, uint32_t cnt) {
    asm volatile("mbarrier.init.shared.b64 [%0], %1;" :: "r"(m), "r"(cnt) : "memory");
}
__device__ __forceinline__ void mbar_arrive(uint32_t m) {
    asm volatile("mbarrier.arrive.release.cta.shared::cta.b64 _, [%0];" :: "r"(m) : "memory");
}
__device__ __forceinline__ void mbar_expect_tx(uint32_t m, uint32_t bytes) {
    asm volatile("mbarrier.arrive.expect_tx.shared.b64 _, [%0], %1;" :: "r"(m), "r"(bytes) : "memory");
}
__device__ __forceinline__ void mbar_wait(uint32_t m, uint32_t ph) {
    uint32_t done;
    asm volatile("{\n\t.reg .pred p;\n\tmbarrier.try_wait.parity.acquire.cta.shared::cta.b64 p, [%1], %2;\n\tselp.b32 %0, 1, 0, p;\n\t}"
                 : "=r"(done) : "r"(m), "r"(ph) : "memory");
    while (!done) {
        asm volatile("{\n\t.reg .pred p;\n\tmbarrier.try_wait.parity.acquire.cta.shared::cta.b64 p, [%1], %2, 0x989680;\n\tselp.b32 %0, 1, 0, p;\n\t}"
                     : "=r"(done) : "r"(m), "r"(ph) : "memory");
    }
}
__device__ __forceinline__ void bulk_g2s(uint32_t dst, const void* src, uint32_t bytes, uint32_t mbar) {
    asm volatile("cp.async.bulk.shared::cluster.global.mbarrier::complete_tx::bytes [%0], [%1], %2, [%3];"
                 :: "r"(dst), "l"(src), "r"(bytes), "r"(mbar) : "memory");
}
__device__ __forceinline__ void ldsm_x4_t(uint32_t* r, uint32_t addr) {
    asm volatile("ldmatrix.sync.aligned.m8n8.x4.trans.shared.b16 {%0,%1,%2,%3}, [%4];"
                 : "=r"(r[0]), "=r"(r[1]), "=r"(r[2]), "=r"(r[3]) : "r"(addr));
}
__device__ __forceinline__ void mma_f16(float* d, const uint32_t* a, const uint32_t* b) {
    asm volatile("mma.sync.aligned.m16n8k16.row.col.f32.f16.f16.f32 "
                 "{%0,%1,%2,%3}, {%4,%5,%6,%7}, {%8,%9}, {%0,%1,%2,%3};"
                 : "+f"(d[0]), "+f"(d[1]), "+f"(d[2]), "+f"(d[3])
                 : "r"(a[0]), "r"(a[1]), "r"(a[2]), "r"(a[3]), "r"(b[0]), "r"(b[1]));
}
__device__ __forceinline__ uint32_t pack_h2(float x, float y) {
    __half2 h = __float22half2_rn(make_float2(x, y));
    return *reinterpret_cast<uint32_t*>(&h);
}

// ---------------------------------------------------------------------------
// Pack A tiles: [mblk][kt] -> 64 k-rows x 272B (128 m fp16 + pad), smem transpose
__global__ void build_Apack_kernel(const float* __restrict__ z, const float* __restrict__ cov) {
    __shared__ __align__(16) __half s[BK][136];
    const int b = blockIdx.x;               // mblk*NKT + kt
    const int mblk = b / NKT, kt = b - mblk * NKT;
    const int m0 = mblk * BM, k0 = kt * BK;
    const int tid = threadIdx.x;
    for (int i = tid; i < BM * BK; i += 256) {
        int m = i >> 6, k = i & 63;
        int col = k0 + k;
        float v = 0.f;
        if (col < ZW)        v = z[(size_t)(m0 + m) * ZW + col];
        else if (col < KDIM) v = cov[(size_t)(m0 + m) * NCROW + (col - ZW)];
        s[k][m] = __float2half(v);
    }
    __syncthreads();
    unsigned char* dst = g_Apack + (size_t)b * A_TILE_B;
    for (int i = tid; i < BK * 17; i += 256) {
        int k = i / 17, c = i - k * 17;
        *reinterpret_cast<uint4*>(dst + k * APITCH + c * 16) =
            *reinterpret_cast<const uint4*>(&s[k][c * 8]);
    }
}

// Pack W tiles: [nblk][kt] -> 64 k-rows x 272B (128 n fp16 + pad), mask fused
__global__ void build_Wpack_kernel(const float* __restrict__ Wm, const float* __restrict__ mask,
                                   const float* __restrict__ Wa, const float* __restrict__ am,
                                   const float* __restrict__ Wc) {
    const size_t total = (size_t)GRID_N * NKT * BK * 17;     // 16B chunks
    size_t idx = (size_t)blockIdx.x * blockDim.x + threadIdx.x;
    if (idx >= total) return;
    int c    = (int)(idx % 17);
    size_t q = idx / 17;
    int k    = (int)(q % BK);
    size_t r = q / BK;
    int kt   = (int)(r % NKT);
    int nblk = (int)(r / NKT);
    unsigned char* dst = g_Wpack + ((size_t)nblk * NKT + kt) * B_TILE_B + k * BPITCH + c * 16;
    int kk = kt * BK + k;
    if (c == 16 || kk >= KDIM) {
        *reinterpret_cast<uint4*>(dst) = make_uint4(0, 0, 0, 0);
        return;
    }
    int n = nblk * BN + c * 8;
    float4 v0, v1;
    if (n + 7 >= NDIM) {
        float t[8];
#pragma unroll
        for (int j = 0; j < 8; j++) {
            int nn = n + j;
            float x = 0.f;
            if (nn < NDIM) {
                if (kk < NPROW)            x = Wm[(size_t)kk * NDIM + nn] * mask[(size_t)kk * NDIM + nn];
                else if (kk < NPROW+NAROW) x = Wa[(size_t)(kk-NPROW) * NDIM + nn] * am[(size_t)(kk-NPROW) * NDIM + nn];
                else                       x = Wc[(size_t)(kk-NPROW-NAROW) * NDIM + nn];
            }
            t[j] = x;
        }
        v0 = make_float4(t[0], t[1], t[2], t[3]);
        v1 = make_float4(t[4], t[5], t[6], t[7]);
    } else if (kk < NPROW) {
        float4 w0 = *reinterpret_cast<const float4*>(Wm + (size_t)kk * NDIM + n);
        float4 w1 = *reinterpret_cast<const float4*>(Wm + (size_t)kk * NDIM + n + 4);
        float4 m0 = *reinterpret_cast<const float4*>(mask + (size_t)kk * NDIM + n);
        float4 m1 = *reinterpret_cast<const float4*>(mask + (size_t)kk * NDIM + n + 4);
        v0 = make_float4(w0.x*m0.x, w0.y*m0.y, w0.z*m0.z, w0.w*m0.w);
        v1 = make_float4(w1.x*m1.x, w1.y*m1.y, w1.z*m1.z, w1.w*m1.w);
    } else if (kk < NPROW + NAROW) {
        int k2 = kk - NPROW;
        float4 w0 = *reinterpret_cast<const float4*>(Wa + (size_t)k2 * NDIM + n);
        float4 w1 = *reinterpret_cast<const float4*>(Wa + (size_t)k2 * NDIM + n + 4);
        float4 m0 = *reinterpret_cast<const float4*>(am + (size_t)k2 * NDIM + n);
        float4 m1 = *reinterpret_cast<const float4*>(am + (size_t)k2 * NDIM + n + 4);
        v0 = make_float4(w0.x*m0.x, w0.y*m0.y, w0.z*m0.z, w0.w*m0.w);
        v1 = make_float4(w1.x*m1.x, w1.y*m1.y, w1.z*m1.z, w1.w*m1.w);
    } else {
        int k2 = kk - NPROW - NAROW;
        v0 = *reinterpret_cast<const float4*>(Wc + (size_t)k2 * NDIM + n);
        v1 = *reinterpret_cast<const float4*>(Wc + (size_t)k2 * NDIM + n + 4);
    }
    uint4 o;
    o.x = pack_h2(v0.x, v0.y); o.y = pack_h2(v0.z, v0.w);
    o.z = pack_h2(v1.x, v1.y); o.w = pack_h2(v1.z, v1.w);
    *reinterpret_cast<uint4*>(dst) = o;
}

// ---------------------------------------------------------------------------
// fp16 mma.sync GEMM (R13 config): 128x128 CTA, 8 warps of 64x32, BK=64,
// 3-stage TMA ring, 2 CTAs/SM. Epilogue: exp -> fp16 scratch + fp32 partials.
__global__ __launch_bounds__(NTHR, 2)
void gemm_exp_kernel() {
    extern __shared__ __align__(16) unsigned char smx[];
    const uint32_t sb0 = smem_u32(smx);          // [0..23] full, [32..55] free
    const int t   = threadIdx.x;
    const int wid = t >> 5;
    const int lid = t & 31;
    const int g4  = lid >> 2;
    const int tig = lid & 3;

    const int per = GROUP * GRID_N;
    int bid = blockIdx.x;
    int grp = bid / per;
    int loc = bid - grp * per;
    int pm  = grp * GROUP + (loc & (GROUP - 1));
    int pn  = loc >> 4;
    const int m0 = pm * BM;
    const int n0 = pn * BN;

    const int wm = wid >> 2;      // 0..1
    const int wn = wid & 3;       // 0..3
    const int mbase = wm * 64;
    const int nbase = wn * 32;

    float acc[4][4][4];
#pragma unroll
    for (int i = 0; i < 4; i++)
#pragma unroll
        for (int j = 0; j < 4; j++)
#pragma unroll
            for (int q = 0; q < 4; q++) acc[i][j][q] = 0.f;

    if (t == 0) {
#pragma unroll
        for (int s = 0; s < STAGES; s++) {
            mbar_init(sb0 + s * 8, 1);           // full: tx-based
            mbar_init(sb0 + 32 + s * 8, 8);      // free: 8 warp arrivals
        }
    }
    __syncthreads();

    const unsigned char* srcA = g_Apack + (size_t)pm * NKT * A_TILE_B;
    const unsigned char* srcB = g_Wpack + (size_t)pn * NKT * B_TILE_B;

    auto issue_stage = [&](int slot, int ks) {
        const uint32_t mb  = sb0 + slot * 8;
        const uint32_t stg = sb0 + 64 + slot * STAGE_B;
        mbar_expect_tx(mb, STAGE_B);
        bulk_g2s(stg,            srcA + (size_t)ks * A_TILE_B, A_TILE_B, mb);
        bulk_g2s(stg + A_TILE_B, srcB + (size_t)ks * B_TILE_B, B_TILE_B, mb);
    };

    if (t == 0) {
#pragma unroll
        for (int s = 0; s < STAGES; s++) issue_stage(s, s);
    }

    const int laneRow = (lid & 7) + ((lid >> 3) & 1) * 8;   // 0..15
    const int laneHi  = (lid >> 4);                          // 0 or 1
    const uint32_t offA = (uint32_t)laneRow * APITCH + (uint32_t)(mbase + laneHi * 8) * 2;
    const uint32_t offB = (uint32_t)laneRow * BPITCH + (uint32_t)(nbase + laneHi * 8) * 2;

    int ph = 0;
    int fpown = 0;
    const bool is_producer = (wid < STAGES) && (lid == 0);
    int slot = 0;

    for (int kt = 0; kt < NKT; kt++) {
        mbar_wait(sb0 + slot * 8, ph);

        const uint32_t stg = sb0 + 64 + slot * STAGE_B;
        const uint32_t pA = stg + offA;
        const uint32_t pB = stg + A_TILE_B + offB;

#pragma unroll
        for (int kk = 0; kk < BK; kk += 16) {
            uint32_t af[4][4], bf[4][2];
#pragma unroll
            for (int mf = 0; mf < 4; mf++) {
                uint32_t r[4];
                ldsm_x4_t(r, pA + kk * APITCH + mf * 32);
                af[mf][0] = r[0]; af[mf][1] = r[2]; af[mf][2] = r[1]; af[mf][3] = r[3];
            }
#pragma unroll
            for (int nf2 = 0; nf2 < 2; nf2++) {
                uint32_t r[4];
                ldsm_x4_t(r, pB + kk * BPITCH + nf2 * 32);
                bf[nf2 * 2][0]     = r[0]; bf[nf2 * 2][1]     = r[1];
                bf[nf2 * 2 + 1][0] = r[2]; bf[nf2 * 2 + 1][1] = r[3];
            }
#pragma unroll
            for (int mf = 0; mf < 4; mf++)
#pragma unroll
                for (int nf = 0; nf < 4; nf++)
                    mma_f16(acc[mf][nf], af[mf], bf[nf]);
        }

        if (lid == 0) mbar_arrive(sb0 + 32 + slot * 8);   // this warp done w/ stage
        if (is_producer && wid == slot && kt + STAGES < NKT) {
            mbar_wait(sb0 + 32 + slot * 8, fpown);        // all 8 warps done
            issue_stage(slot, kt + STAGES);
            fpown ^= 1;
        }
        if (slot == STAGES - 1) { slot = 0; ph ^= 1; } else slot++;
    }

    // ---- epilogue: exp -> fp16 scratch (half2 stores) + fp32 row partials ----
#pragma unroll
    for (int mf = 0; mf < 4; mf++) {
        const int r0 = mbase + mf * 16 + g4;
        __half* e0p = g_exp + (size_t)(m0 + r0) * NDIM;
        __half* e1p = e0p + (size_t)8 * NDIM;
        float s0 = 0.f, s1 = 0.f;
#pragma unroll
        for (int nf = 0; nf < 4; nf++) {
            const int n = n0 + nbase + nf * 8 + tig * 2;
            if (n < NDIM) {
                float e0 = __expf(acc[mf][nf][0]);
                float e1 = __expf(acc[mf][nf][1]);
                float e2 = __expf(acc[mf][nf][2]);
                float e3 = __expf(acc[mf][nf][3]);
                *reinterpret_cast<uint32_t*>(e0p + n) = pack_h2(e0, e1);
                *reinterpret_cast<uint32_t*>(e1p + n) = pack_h2(e2, e3);
                s0 += e0 + e1; s1 += e2 + e3;
            }
        }
        s0 += __shfl_xor_sync(0xffffffffu, s0, 1);
        s0 += __shfl_xor_sync(0xffffffffu, s0, 2);
        s1 += __shfl_xor_sync(0xffffffffu, s1, 1);
        s1 += __shfl_xor_sync(0xffffffffu, s1, 2);
        if (tig == 0) {
            g_part[(size_t)(m0 + r0)     * PW + pn * 4 + wn] = s0;
            g_part[(size_t)(m0 + r0 + 8) * PW + pn * 4 + wn] = s1;
        }
    }
}

// ---------------------------------------------------------------------------
__global__ void reduce_kernel(const float* __restrict__ loglib) {
    __shared__ float red[4];
    int row = blockIdx.x;
    float s = 0.f;
    for (int i = threadIdx.x; i < PW; i += 128) s += g_part[(size_t)row * PW + i];
#pragma unroll
    for (int o = 16; o > 0; o >>= 1) s += __shfl_down_sync(0xffffffffu, s, o);
    int lane = threadIdx.x & 31, warp = threadIdx.x >> 5;
    if (lane == 0) red[warp] = s;
    __syncthreads();
    if (threadIdx.x == 0) {
        float tot = red[0] + red[1] + red[2] + red[3];
        g_scale[row] = expf(loglib[row]) / tot;
    }
}

// Read fp16 exp, scale, write fp32 out. 8 halves per thread.
__global__ void scale_convert_kernel(float* __restrict__ out) {
    const int C8 = NDIM / 8;                    // 2500
    int row = blockIdx.y;
    int c8  = blockIdx.x * blockDim.x + threadIdx.x;
    if (c8 >= C8) return;
    float s = g_scale[row];
    uint4 h = *(reinterpret_cast<const uint4*>(g_exp + (size_t)row * NDIM) + c8);
    float2 a = __half22float2(*reinterpret_cast<__half2*>(&h.x));
    float2 b = __half22float2(*reinterpret_cast<__half2*>(&h.y));
    float2 c = __half22float2(*reinterpret_cast<__half2*>(&h.z));
    float2 d = __half22float2(*reinterpret_cast<__half2*>(&h.w));
    float4 o0 = make_float4(a.x * s, a.y * s, b.x * s, b.y * s);
    float4 o1 = make_float4(c.x * s, c.y * s, d.x * s, d.y * s);
    float4* dst = reinterpret_cast<float4*>(out + (size_t)row * NDIM + c8 * 8);
    dst[0] = o0;
    dst[1] = o1;
}

// ---------------------------------------------------------------------------
extern "C" void kernel_launch(void* const* d_in, const int* in_sizes, int n_in,
                              void* d_out, int out_size) {
    const float* z      = (const float*)d_in[0];
    const float* loglib = (const float*)d_in[1];
    const float* cov    = (const float*)d_in[2];
    const float* mask   = (const float*)d_in[3];
    const float* amask  = (const float*)d_in[4];
    const float* Wm     = (const float*)d_in[5];
    const float* Wa     = (const float*)d_in[6];
    const float* Wc     = (const float*)d_in[7];
    float* out = (float*)d_out;

    cudaFuncSetAttribute(gemm_exp_kernel, cudaFuncAttributeMaxDynamicSharedMemorySize, SMEM_BYTES);

    build_Apack_kernel<<<GRID_M * NKT, 256>>>(z, cov);
    {
        size_t total = (size_t)GRID_N * NKT * BK * 17;
        build_Wpack_kernel<<<(unsigned)((total + 255) / 256), 256>>>(Wm, mask, Wa, amask, Wc);
    }
    gemm_exp_kernel<<<GRID_M * GRID_N, NTHR, SMEM_BYTES>>>();
    reduce_kernel<<<BDIM, 128>>>(loglib);
    {
        dim3 gridS((NDIM / 8 + 255) / 256, BDIM, 1);
        scale_convert_kernel<<<gridS, 256>>>(out);
    }
}